// round 7
// baseline (speedup 1.0000x reference)
#include <cuda_runtime.h>
#include <cuda_bf16.h>
#include <cstdint>

#define NN   4096
#define FF   256
#define KH   8
#define FPD  64
#define KFP  512   // K*FP

// ---------------- scratch (static device globals; no allocation) -------------
__device__ float g_hl[KH * NN];                   // hl[k][n]
__device__ float g_hr[KH * NN];                   // hr[k][n]
__device__ unsigned int g_maskbT[(NN / 32) * NN]; // 2 MB bits: [m_word][n]
__device__ int g_mask_fmt;                        // 0=uint8, else 4-byte words
__device__ __nv_bfloat16 g_xeT_hi[KH * FPD * NN]; // 4 MB: hi(xe)[k][f][n]
__device__ __nv_bfloat16 g_xeT_lo[KH * FPD * NN]; // 4 MB: lo(xe)[k][f][n]

// =================== helpers (baseline PTX only: ldmatrix + mma.sync) =======
__device__ __forceinline__ uint32_t smem_u32(const void* p) {
    uint32_t a;
    asm("{ .reg .u64 t; cvta.to.shared.u64 t, %1; cvt.u32.u64 %0, t; }" : "=r"(a) : "l"(p));
    return a;
}
// pack bf16x2: lo-half = cvt(x), hi-half = cvt(y)
__device__ __forceinline__ uint32_t bf16x2(float x, float y) {
    uint32_t r;
    asm("cvt.rn.bf16x2.f32 %0, %1, %2;" : "=r"(r) : "f"(y), "f"(x));
    return r;
}
#define LDSM4(R0, R1, R2, R3, A) \
    asm volatile("ldmatrix.sync.aligned.m8n8.x4.shared.b16 {%0,%1,%2,%3}, [%4];" \
                 : "=r"(R0), "=r"(R1), "=r"(R2), "=r"(R3) : "r"(A))
#define MMA16816(D, A0, A1, A2, A3, B0, B1) \
    asm volatile("mma.sync.aligned.m16n8k16.row.col.f32.bf16.bf16.f32 " \
                 "{%0,%1,%2,%3}, {%4,%5,%6,%7}, {%8,%9}, {%0,%1,%2,%3};" \
                 : "+f"((D)[0]), "+f"((D)[1]), "+f"((D)[2]), "+f"((D)[3]) \
                 : "r"(A0), "r"(A1), "r"(A2), "r"(A3), "r"(B0), "r"(B1))

__device__ __forceinline__ float pcalc(float hl, float hr, unsigned bit) {
    float s = hl + hr;
    float l = fmaxf(s, 0.2f * s);       // LeakyReLU(0.2)
    float e = __expf(l);
    return bit ? e : 0.0f;              // masked -> exactly 0
}

// ---------------- Kernel 0: probe mask dtype --------------------------------
__global__ void detect_mask_fmt(const unsigned int* __restrict__ m) {
    int lane = threadIdx.x;
    bool not_i32 = false, not_f32 = false;
    for (int i = lane; i < 4096; i += 32) {
        unsigned int w = m[i];
        if (w > 1u) not_i32 = true;
        if (w != 0u && w != 0x3F800000u) not_f32 = true;
    }
    unsigned a = __ballot_sync(0xFFFFFFFFu, not_i32);
    unsigned b = __ballot_sync(0xFFFFFFFFu, not_f32);
    if (lane == 0) g_mask_fmt = (a == 0u) ? 1 : ((b == 0u) ? 2 : 0);
}

// ---------------- Kernel 0b: mask -> transposed bitfield --------------------
// g_maskbT[wm * NN + n], bit j of word = mask[n][32*wm + j]
__global__ void __launch_bounds__(256) mask_canon_bits(const void* __restrict__ m) {
    int idx = blockIdx.x * 256 + threadIdx.x;   // 0..524287
    int n  = idx >> 7;
    int wm = idx & 127;
    unsigned bits = 0;
    if (g_mask_fmt != 0) {
        const uint4* p = (const uint4*)((const unsigned int*)m + (size_t)n * NN + wm * 32);
#pragma unroll
        for (int q = 0; q < 8; q++) {
            uint4 v = p[q];
            bits |= (v.x != 0u) << (q * 4 + 0);
            bits |= (v.y != 0u) << (q * 4 + 1);
            bits |= (v.z != 0u) << (q * 4 + 2);
            bits |= (v.w != 0u) << (q * 4 + 3);
        }
    } else {
        const uint4* p = (const uint4*)((const unsigned char*)m + (size_t)n * NN + wm * 32);
#pragma unroll
        for (int q = 0; q < 2; q++) {
            uint4 v = p[q];
            unsigned w[4] = {v.x, v.y, v.z, v.w};
#pragma unroll
            for (int c = 0; c < 4; c++)
#pragma unroll
                for (int e = 0; e < 4; e++)
                    bits |= (((w[c] >> (e * 8)) & 0xFFu) != 0u) << (q * 16 + c * 4 + e);
        }
    }
    g_maskbT[(size_t)wm * NN + n] = bits;
}

// ---------------- Kernel A: xe GEMM + fused hl/hr + bf16 hi/lo transpose ----
__global__ void __launch_bounds__(256) gemm_xe(const float* __restrict__ x,
                                               const float* __restrict__ W,
                                               const float* __restrict__ b,
                                               const float* __restrict__ al,
                                               const float* __restrict__ ar) {
    __shared__ float a_s[16][128];
    __shared__ float b_s[16][64];
    const int tid = threadIdx.x;
    const int tx = tid & 15;
    const int ty = tid >> 4;
    const int row0 = blockIdx.x * 128;
    const int k    = blockIdx.y;          // head
    const int col0 = k * 64;

    float acc[8][4];
#pragma unroll
    for (int i = 0; i < 8; i++)
#pragma unroll
        for (int j = 0; j < 4; j++) acc[i][j] = 0.0f;

    for (int k0 = 0; k0 < FF; k0 += 16) {
#pragma unroll
        for (int u = 0; u < 2; u++) {
            int f4 = tid * 2 + u;
            int r  = f4 >> 2;
            int c4 = f4 & 3;
            float4 v = *(const float4*)&x[(size_t)(row0 + r) * FF + k0 + c4 * 4];
            a_s[c4 * 4 + 0][r] = v.x; a_s[c4 * 4 + 1][r] = v.y;
            a_s[c4 * 4 + 2][r] = v.z; a_s[c4 * 4 + 3][r] = v.w;
        }
        {
            int o  = tid >> 2;
            int c4 = tid & 3;
            float4 v = *(const float4*)&W[(size_t)(col0 + o) * FF + k0 + c4 * 4];
            b_s[c4 * 4 + 0][o] = v.x; b_s[c4 * 4 + 1][o] = v.y;
            b_s[c4 * 4 + 2][o] = v.z; b_s[c4 * 4 + 3][o] = v.w;
        }
        __syncthreads();
#pragma unroll
        for (int kk = 0; kk < 16; kk++) {
            float a_f[8], b_f[4];
#pragma unroll
            for (int i = 0; i < 8; i++) a_f[i] = a_s[kk][ty * 8 + i];
#pragma unroll
            for (int j = 0; j < 4; j++) b_f[j] = b_s[kk][tx * 4 + j];
#pragma unroll
            for (int i = 0; i < 8; i++)
#pragma unroll
                for (int j = 0; j < 4; j++) acc[i][j] += a_f[i] * b_f[j];
        }
        __syncthreads();
    }
    float4 bias = *(const float4*)&b[col0 + tx * 4];
#pragma unroll
    for (int i = 0; i < 8; i++) {
        acc[i][0] += bias.x; acc[i][1] += bias.y;
        acc[i][2] += bias.z; acc[i][3] += bias.w;
    }
    // ---- fused hl/hr: partial dot over this thread's 4 f, reduce over tx ----
    float4 al4 = *(const float4*)&al[k * FPD + tx * 4];
    float4 ar4 = *(const float4*)&ar[k * FPD + tx * 4];
#pragma unroll
    for (int i = 0; i < 8; i++) {
        float l = acc[i][0] * al4.x + acc[i][1] * al4.y + acc[i][2] * al4.z + acc[i][3] * al4.w;
        float r = acc[i][0] * ar4.x + acc[i][1] * ar4.y + acc[i][2] * ar4.z + acc[i][3] * ar4.w;
#pragma unroll
        for (int off = 8; off; off >>= 1) {
            l += __shfl_xor_sync(0xFFFFFFFFu, l, off);
            r += __shfl_xor_sync(0xFFFFFFFFu, r, off);
        }
        if (tx == 0) {
            g_hl[k * NN + row0 + ty * 8 + i] = l;
            g_hr[k * NN + row0 + ty * 8 + i] = r;
        }
    }
    // ---- bf16 hi/lo split transpose: g_xeT_*[k][f][n] ----
#pragma unroll
    for (int j = 0; j < 4; j++) {
        uint32_t hp[4], lp[4];
#pragma unroll
        for (int i2 = 0; i2 < 4; i2++) {
            float v0 = acc[2 * i2][j], v1 = acc[2 * i2 + 1][j];
            uint32_t b0 = __float_as_uint(v0), b1 = __float_as_uint(v1);
            hp[i2] = __byte_perm(b0, b1, 0x7632);               // trunc-to-bf16 pair
            float l0 = v0 - __uint_as_float(b0 & 0xFFFF0000u);
            float l1 = v1 - __uint_as_float(b1 & 0xFFFF0000u);
            lp[i2] = bf16x2(l0, l1);
        }
        size_t base = ((size_t)(k * FPD + tx * 4 + j)) * NN + row0 + ty * 8;
        *(uint4*)&g_xeT_hi[base] = make_uint4(hp[0], hp[1], hp[2], hp[3]);
        *(uint4*)&g_xeT_lo[base] = make_uint4(lp[0], lp[1], lp[2], lp[3]);
    }
}

// ---------------- Kernel C: attention via mma.sync bf16 (split 3xMMA) -------
// CTA = (head k, 128 n-rows). Warp w owns rows 16w..16w+15, all 64 f.
// Phase-major MMA issue: per t, hoist all 4 pr LDSMs, then 8 independent
// Phi*Vhi MMAs, 8 Plo*Vhi (vh frags still live), reload frags as vl,
// 8 Phi*Vlo. Same-accumulator reuse distance = 8 MMAs -> fully pipelined.
#define MCH 64
__global__ void __launch_bounds__(256, 2) gat_attn_mma(float* __restrict__ out) {
    __shared__ __align__(16) __nv_bfloat16 s_vhi[2][MCH * 72];  // rows padded to 72 halves
    __shared__ __align__(16) __nv_bfloat16 s_vlo[2][MCH * 72];
    __shared__ float s_hr[2][MCH];
    __shared__ uint32_t s_mb[2][128 * 2];

    const int tid  = threadIdx.x;
    const int lane = tid & 31;
    const int warp = tid >> 5;
    const int k    = blockIdx.y;
    const int n0   = blockIdx.x * 128;
    const int g    = lane >> 2;
    const int q    = lane & 3;
    const int r0   = warp * 16 + g;
    const int r1   = r0 + 8;

    const float hl0 = g_hl[k * NN + n0 + r0];
    const float hl1 = g_hl[k * NN + n0 + r1];

    float d[8][4];
#pragma unroll
    for (int nt = 0; nt < 8; nt++)
#pragma unroll
        for (int e = 0; e < 4; e++) d[nt][e] = 0.0f;
    float rs0 = 0.0f, rs1 = 0.0f;

    const uint32_t vb_hi0 = smem_u32(s_vhi[0]);
    const uint32_t vb_lo0 = smem_u32(s_vlo[0]);
    const uint32_t lm_row  = ((lane & 16) >> 1) + (lane & 7);   // 0..15
    const uint32_t lm_koff = (lane & 8) ? 16u : 0u;

    const int pf_r  = tid & 127;                  // mask row
    const int pf_w  = tid >> 7;                   // mask word (0..1)

    uint4 vreg[4];
    float hreg;
    uint32_t mreg;

    // ---- prologue: prefetch chunk 0 ----
    {
        const int m0 = 0;
#pragma unroll
        for (int u = 0; u < 4; u++) {
            int idx = u * 256 + tid;
            int sel = idx >> 9;
            int rem = idx & 511;
            int f = rem >> 3, mo = (rem & 7) * 8;
            vreg[u] = *(const uint4*)((sel ? g_xeT_lo : g_xeT_hi)
                        + ((size_t)(k * FPD + f)) * NN + m0 + mo);
        }
        hreg = (tid < MCH) ? g_hr[k * NN + m0 + tid] : 0.0f;
        mreg = g_maskbT[(size_t)(m0 / 32 + pf_w) * NN + n0 + pf_r];
#pragma unroll
        for (int u = 0; u < 4; u++) {
            int idx = u * 256 + tid;
            int sel = idx >> 9;
            int rem = idx & 511;
            int f = rem >> 3, mo = (rem & 7) * 8;
            *(uint4*)((sel ? s_vlo[0] : s_vhi[0]) + f * 72 + mo) = vreg[u];
        }
        if (tid < MCH) s_hr[0][tid] = hreg;
        s_mb[0][pf_r * 2 + pf_w] = mreg;
        __syncthreads();
    }

#pragma unroll 1
    for (int c = 0; c < NN / MCH; c++) {
        const int st = c & 1;
        const bool more = (c + 1 < NN / MCH);
        // ---- prefetch chunk c+1 into regs (overlaps MMA below) ----
        if (more) {
            const int m0 = (c + 1) * MCH;
#pragma unroll
            for (int u = 0; u < 4; u++) {
                int idx = u * 256 + tid;
                int sel = idx >> 9;
                int rem = idx & 511;
                int f = rem >> 3, mo = (rem & 7) * 8;
                vreg[u] = *(const uint4*)((sel ? g_xeT_lo : g_xeT_hi)
                            + ((size_t)(k * FPD + f)) * NN + m0 + mo);
            }
            hreg = (tid < MCH) ? g_hr[k * NN + m0 + tid] : 0.0f;
            mreg = g_maskbT[(size_t)(m0 / 32 + pf_w) * NN + n0 + pf_r];
        }

        // ---- compute on stage st ----
        uint32_t mb0[2], mb1[2];
        *(uint2*)mb0 = *(const uint2*)&s_mb[st][r0 * 2];
        *(uint2*)mb1 = *(const uint2*)&s_mb[st][r1 * 2];
        const uint32_t vbh = vb_hi0 + st * (MCH * 72 * 2);
        const uint32_t vbl = vb_lo0 + st * (MCH * 72 * 2);

#pragma unroll
        for (int t = 0; t < 4; t++) {
            // ---- P-gen for this lane's A-fragment slots ----
            float2 hA = *(const float2*)&s_hr[st][t * 16 + q * 2];
            float2 hB = *(const float2*)&s_hr[st][t * 16 + q * 2 + 8];
            uint32_t w0 = mb0[t >> 1], w1 = mb1[t >> 1];
            int sh = (t & 1) * 16 + q * 2;
            float p00 = pcalc(hl0, hA.x, (w0 >> sh) & 1u);
            float p01 = pcalc(hl0, hA.y, (w0 >> (sh + 1)) & 1u);
            float p02 = pcalc(hl0, hB.x, (w0 >> (sh + 8)) & 1u);
            float p03 = pcalc(hl0, hB.y, (w0 >> (sh + 9)) & 1u);
            float p10 = pcalc(hl1, hA.x, (w1 >> sh) & 1u);
            float p11 = pcalc(hl1, hA.y, (w1 >> (sh + 1)) & 1u);
            float p12 = pcalc(hl1, hB.x, (w1 >> (sh + 8)) & 1u);
            float p13 = pcalc(hl1, hB.y, (w1 >> (sh + 9)) & 1u);
            rs0 += (p00 + p01) + (p02 + p03);
            rs1 += (p10 + p11) + (p12 + p13);

            uint32_t b00 = __float_as_uint(p00), b01 = __float_as_uint(p01);
            uint32_t b10 = __float_as_uint(p10), b11 = __float_as_uint(p11);
            uint32_t b02 = __float_as_uint(p02), b03 = __float_as_uint(p03);
            uint32_t b12 = __float_as_uint(p12), b13 = __float_as_uint(p13);
            uint32_t ah0 = __byte_perm(b00, b01, 0x7632);
            uint32_t ah1 = __byte_perm(b10, b11, 0x7632);
            uint32_t ah2 = __byte_perm(b02, b03, 0x7632);
            uint32_t ah3 = __byte_perm(b12, b13, 0x7632);
            uint32_t al0 = bf16x2(p00 - __uint_as_float(b00 & 0xFFFF0000u),
                                  p01 - __uint_as_float(b01 & 0xFFFF0000u));
            uint32_t al1 = bf16x2(p10 - __uint_as_float(b10 & 0xFFFF0000u),
                                  p11 - __uint_as_float(b11 & 0xFFFF0000u));
            uint32_t al2 = bf16x2(p02 - __uint_as_float(b02 & 0xFFFF0000u),
                                  p03 - __uint_as_float(b03 & 0xFFFF0000u));
            uint32_t al3 = bf16x2(p12 - __uint_as_float(b12 & 0xFFFF0000u),
                                  p13 - __uint_as_float(b13 & 0xFFFF0000u));

            // ---- hoist all hi-V fragments for the 4 pr tiles ----
            uint32_t vA[4], vB[4], vC[4], vD[4];
#pragma unroll
            for (int pr = 0; pr < 4; pr++) {
                uint32_t a = (pr * 16 + lm_row) * 144 + t * 32 + lm_koff;
                LDSM4(vA[pr], vB[pr], vC[pr], vD[pr], vbh + a);
            }
            // Phase 1: Phi * Vhi  (8 independent accumulators)
#pragma unroll
            for (int pr = 0; pr < 4; pr++) {
                MMA16816(d[2 * pr],     ah0, ah1, ah2, ah3, vA[pr], vB[pr]);
                MMA16816(d[2 * pr + 1], ah0, ah1, ah2, ah3, vC[pr], vD[pr]);
            }
            // Phase 2: Plo * Vhi  (vh frags still live, reuse distance 8)
#pragma unroll
            for (int pr = 0; pr < 4; pr++) {
                MMA16816(d[2 * pr],     al0, al1, al2, al3, vA[pr], vB[pr]);
                MMA16816(d[2 * pr + 1], al0, al1, al2, al3, vC[pr], vD[pr]);
            }
            // ---- reload fragments as lo-V (same registers) ----
#pragma unroll
            for (int pr = 0; pr < 4; pr++) {
                uint32_t a = (pr * 16 + lm_row) * 144 + t * 32 + lm_koff;
                LDSM4(vA[pr], vB[pr], vC[pr], vD[pr], vbl + a);
            }
            // Phase 3: Phi * Vlo
#pragma unroll
            for (int pr = 0; pr < 4; pr++) {
                MMA16816(d[2 * pr],     ah0, ah1, ah2, ah3, vA[pr], vB[pr]);
                MMA16816(d[2 * pr + 1], ah0, ah1, ah2, ah3, vC[pr], vD[pr]);
            }
        }

        // ---- store prefetched chunk to alternate stage ----
        if (more) {
            const int st1 = 1 - st;
#pragma unroll
            for (int u = 0; u < 4; u++) {
                int idx = u * 256 + tid;
                int sel = idx >> 9;
                int rem = idx & 511;
                int f = rem >> 3, mo = (rem & 7) * 8;
                *(uint4*)((sel ? s_vlo[st1] : s_vhi[st1]) + f * 72 + mo) = vreg[u];
            }
            if (tid < MCH) s_hr[st1][tid] = hreg;
            s_mb[st1][pf_r * 2 + pf_w] = mreg;
            __syncthreads();
        }
    }

    // ---- epilogue: rowsum (quad reduce), normalize, double-ELU, store ----
    rs0 += __shfl_xor_sync(0xFFFFFFFFu, rs0, 1);
    rs0 += __shfl_xor_sync(0xFFFFFFFFu, rs0, 2);
    rs1 += __shfl_xor_sync(0xFFFFFFFFu, rs1, 1);
    rs1 += __shfl_xor_sync(0xFFFFFFFFu, rs1, 2);
    const float i0 = 1.0f / rs0;
    const float i1 = 1.0f / rs1;
    float* o0 = out + (size_t)(n0 + r0) * KFP + k * FPD + 2 * q;
    float* o1 = out + (size_t)(n0 + r1) * KFP + k * FPD + 2 * q;
#pragma unroll
    for (int nt = 0; nt < 8; nt++) {
        float z0 = d[nt][0] * i0, z1 = d[nt][1] * i0;
        float z2 = d[nt][2] * i1, z3 = d[nt][3] * i1;
        z0 = z0 > 0.f ? z0 : expm1f(z0); z0 = z0 > 0.f ? z0 : expm1f(z0);
        z1 = z1 > 0.f ? z1 : expm1f(z1); z1 = z1 > 0.f ? z1 : expm1f(z1);
        z2 = z2 > 0.f ? z2 : expm1f(z2); z2 = z2 > 0.f ? z2 : expm1f(z2);
        z3 = z3 > 0.f ? z3 : expm1f(z3); z3 = z3 > 0.f ? z3 : expm1f(z3);
        *(float2*)(o0 + nt * 8) = make_float2(z0, z1);
        *(float2*)(o1 + nt * 8) = make_float2(z2, z3);
    }
}

// ---------------- optional: mask passthrough as float -----------------------
__global__ void mask_to_float(float* __restrict__ o, int n) {
    int i = blockIdx.x * blockDim.x + threadIdx.x;
    if (i < n) {
        int row = i >> 12, m = i & 4095;
        unsigned b = (g_maskbT[(size_t)(m >> 5) * NN + row] >> (m & 31)) & 1u;
        o[i] = (float)b;
    }
}

// ---------------- launch -----------------------------------------------------
extern "C" void kernel_launch(void* const* d_in, const int* in_sizes, int n_in,
                              void* d_out, int out_size) {
    const float* x  = (const float*)d_in[0];
    const float* W  = (const float*)d_in[1];
    const float* b  = (const float*)d_in[2];
    const float* al = (const float*)d_in[3];
    const float* ar = (const float*)d_in[4];
    const void*  m  = d_in[5];
    float* out = (float*)d_out;

    detect_mask_fmt<<<1, 32>>>((const unsigned int*)m);
    mask_canon_bits<<<(NN * NN / 32) / 256, 256>>>(m);
    gemm_xe<<<dim3(32, 8), 256>>>(x, W, b, al, ar);
    gat_attn_mma<<<dim3(32, 8), 256>>>(out);

    const int OUT_ELEMS  = NN * KFP;
    const int MASK_ELEMS = NN * NN;
    if (out_size >= OUT_ELEMS + MASK_ELEMS) {
        mask_to_float<<<(MASK_ELEMS + 255) / 256, 256>>>(out + OUT_ELEMS, MASK_ELEMS);
    }
}

// round 8
// speedup vs baseline: 1.4144x; 1.4144x over previous
#include <cuda_runtime.h>
#include <cuda_fp16.h>
#include <cstdint>

#define NN   4096
#define FF   256
#define KH   8
#define FPD  64
#define KFP  512   // K*FP
#define LOG2E 1.4426950408889634f

// ---------------- scratch (static device globals; no allocation) -------------
__device__ float g_hl[KH * NN];                   // hl[k][n] * log2(e)
__device__ float g_hr[KH * NN];                   // hr[k][n] * log2(e)
__device__ unsigned int g_maskbT[(NN / 32) * NN]; // 2 MB bits: [m_word][n]
__device__ int g_mask_fmt;                        // 0=uint8, else 4-byte words
__device__ unsigned short g_xeT_h[KH * FPD * NN]; // 4 MB: fp16(xe)[k][f][n]

// =================== helpers (baseline PTX only: ldmatrix + mma.sync) =======
__device__ __forceinline__ uint32_t smem_u32(const void* p) {
    uint32_t a;
    asm("{ .reg .u64 t; cvta.to.shared.u64 t, %1; cvt.u32.u64 %0, t; }" : "=r"(a) : "l"(p));
    return a;
}
// pack fp16x2: lo-half = cvt(x), hi-half = cvt(y)
__device__ __forceinline__ uint32_t h16x2(float x, float y) {
    uint32_t r;
    asm("cvt.rn.f16x2.f32 %0, %1, %2;" : "=r"(r) : "f"(y), "f"(x));
    return r;
}
__device__ __forceinline__ float ex2f(float x) {
    float r;
    asm("ex2.approx.ftz.f32 %0, %1;" : "=f"(r) : "f"(x));
    return r;
}
#define LDSM4(R0, R1, R2, R3, A) \
    asm volatile("ldmatrix.sync.aligned.m8n8.x4.shared.b16 {%0,%1,%2,%3}, [%4];" \
                 : "=r"(R0), "=r"(R1), "=r"(R2), "=r"(R3) : "r"(A))
#define LDSM2(R0, R1, A) \
    asm volatile("ldmatrix.sync.aligned.m8n8.x2.shared.b16 {%0,%1}, [%2];" \
                 : "=r"(R0), "=r"(R1) : "r"(A))
#define MMAH(D, A0, A1, A2, A3, B0, B1) \
    asm volatile("mma.sync.aligned.m16n8k16.row.col.f32.f16.f16.f32 " \
                 "{%0,%1,%2,%3}, {%4,%5,%6,%7}, {%8,%9}, {%0,%1,%2,%3};" \
                 : "+f"((D)[0]), "+f"((D)[1]), "+f"((D)[2]), "+f"((D)[3]) \
                 : "r"(A0), "r"(A1), "r"(A2), "r"(A3), "r"(B0), "r"(B1))

// exp2(lrelu(s)) with pre-scaled inputs (lrelu commutes with positive scale)
__device__ __forceinline__ float pcalc(float hl2, float hr2) {
    float s = hl2 + hr2;
    float l = fmaxf(s, 0.2f * s);
    return ex2f(l);
}
// AND-pattern for packed fp16x2 from 2 mask bits at positions s, s+1
__device__ __forceinline__ uint32_t andpat(uint32_t w, int s) {
    return ((w >> s) & 1u) * 0xFFFFu | ((w >> (s + 1)) & 1u) * 0xFFFF0000u;
}

// ---------------- Kernel 0: probe mask dtype --------------------------------
__global__ void detect_mask_fmt(const unsigned int* __restrict__ m) {
    int lane = threadIdx.x;
    bool not_i32 = false, not_f32 = false;
    for (int i = lane; i < 4096; i += 32) {
        unsigned int w = m[i];
        if (w > 1u) not_i32 = true;
        if (w != 0u && w != 0x3F800000u) not_f32 = true;
    }
    unsigned a = __ballot_sync(0xFFFFFFFFu, not_i32);
    unsigned b = __ballot_sync(0xFFFFFFFFu, not_f32);
    if (lane == 0) g_mask_fmt = (a == 0u) ? 1 : ((b == 0u) ? 2 : 0);
}

// ---------------- Kernel 0b: mask -> transposed bitfield --------------------
__global__ void __launch_bounds__(256) mask_canon_bits(const void* __restrict__ m) {
    int idx = blockIdx.x * 256 + threadIdx.x;   // 0..524287
    int n  = idx >> 7;
    int wm = idx & 127;
    unsigned bits = 0;
    if (g_mask_fmt != 0) {
        const uint4* p = (const uint4*)((const unsigned int*)m + (size_t)n * NN + wm * 32);
#pragma unroll
        for (int q = 0; q < 8; q++) {
            uint4 v = p[q];
            bits |= (v.x != 0u) << (q * 4 + 0);
            bits |= (v.y != 0u) << (q * 4 + 1);
            bits |= (v.z != 0u) << (q * 4 + 2);
            bits |= (v.w != 0u) << (q * 4 + 3);
        }
    } else {
        const uint4* p = (const uint4*)((const unsigned char*)m + (size_t)n * NN + wm * 32);
#pragma unroll
        for (int q = 0; q < 2; q++) {
            uint4 v = p[q];
            unsigned w[4] = {v.x, v.y, v.z, v.w};
#pragma unroll
            for (int c = 0; c < 4; c++)
#pragma unroll
                for (int e = 0; e < 4; e++)
                    bits |= (((w[c] >> (e * 8)) & 0xFFu) != 0u) << (q * 16 + c * 4 + e);
        }
    }
    g_maskbT[(size_t)wm * NN + n] = bits;
}

// ---------------- Kernel A: xe GEMM + fused hl/hr + fp16 transpose ----------
__global__ void __launch_bounds__(256) gemm_xe(const float* __restrict__ x,
                                               const float* __restrict__ W,
                                               const float* __restrict__ b,
                                               const float* __restrict__ al,
                                               const float* __restrict__ ar) {
    __shared__ float a_s[16][128];
    __shared__ float b_s[16][64];
    const int tid = threadIdx.x;
    const int tx = tid & 15;
    const int ty = tid >> 4;
    const int row0 = blockIdx.x * 128;
    const int k    = blockIdx.y;          // head
    const int col0 = k * 64;

    float acc[8][4];
#pragma unroll
    for (int i = 0; i < 8; i++)
#pragma unroll
        for (int j = 0; j < 4; j++) acc[i][j] = 0.0f;

    for (int k0 = 0; k0 < FF; k0 += 16) {
#pragma unroll
        for (int u = 0; u < 2; u++) {
            int f4 = tid * 2 + u;
            int r  = f4 >> 2;
            int c4 = f4 & 3;
            float4 v = *(const float4*)&x[(size_t)(row0 + r) * FF + k0 + c4 * 4];
            a_s[c4 * 4 + 0][r] = v.x; a_s[c4 * 4 + 1][r] = v.y;
            a_s[c4 * 4 + 2][r] = v.z; a_s[c4 * 4 + 3][r] = v.w;
        }
        {
            int o  = tid >> 2;
            int c4 = tid & 3;
            float4 v = *(const float4*)&W[(size_t)(col0 + o) * FF + k0 + c4 * 4];
            b_s[c4 * 4 + 0][o] = v.x; b_s[c4 * 4 + 1][o] = v.y;
            b_s[c4 * 4 + 2][o] = v.z; b_s[c4 * 4 + 3][o] = v.w;
        }
        __syncthreads();
#pragma unroll
        for (int kk = 0; kk < 16; kk++) {
            float a_f[8], b_f[4];
#pragma unroll
            for (int i = 0; i < 8; i++) a_f[i] = a_s[kk][ty * 8 + i];
#pragma unroll
            for (int j = 0; j < 4; j++) b_f[j] = b_s[kk][tx * 4 + j];
#pragma unroll
            for (int i = 0; i < 8; i++)
#pragma unroll
                for (int j = 0; j < 4; j++) acc[i][j] += a_f[i] * b_f[j];
        }
        __syncthreads();
    }
    float4 bias = *(const float4*)&b[col0 + tx * 4];
#pragma unroll
    for (int i = 0; i < 8; i++) {
        acc[i][0] += bias.x; acc[i][1] += bias.y;
        acc[i][2] += bias.z; acc[i][3] += bias.w;
    }
    // ---- fused hl/hr (scaled by log2e): partial dot, reduce over tx ----
    float4 al4 = *(const float4*)&al[k * FPD + tx * 4];
    float4 ar4 = *(const float4*)&ar[k * FPD + tx * 4];
#pragma unroll
    for (int i = 0; i < 8; i++) {
        float l = acc[i][0] * al4.x + acc[i][1] * al4.y + acc[i][2] * al4.z + acc[i][3] * al4.w;
        float r = acc[i][0] * ar4.x + acc[i][1] * ar4.y + acc[i][2] * ar4.z + acc[i][3] * ar4.w;
#pragma unroll
        for (int off = 8; off; off >>= 1) {
            l += __shfl_xor_sync(0xFFFFFFFFu, l, off);
            r += __shfl_xor_sync(0xFFFFFFFFu, r, off);
        }
        if (tx == 0) {
            g_hl[k * NN + row0 + ty * 8 + i] = l * LOG2E;
            g_hr[k * NN + row0 + ty * 8 + i] = r * LOG2E;
        }
    }
    // ---- fp16 transpose: g_xeT_h[k][f][n] ----
#pragma unroll
    for (int j = 0; j < 4; j++) {
        uint32_t hp[4];
#pragma unroll
        for (int i2 = 0; i2 < 4; i2++)
            hp[i2] = h16x2(acc[2 * i2][j], acc[2 * i2 + 1][j]);
        size_t base = ((size_t)(k * FPD + tx * 4 + j)) * NN + row0 + ty * 8;
        *(uint4*)&g_xeT_h[base] = make_uint4(hp[0], hp[1], hp[2], hp[3]);
    }
}

// ---------------- Kernel C: attention via fp16 mma.sync ---------------------
// CTA = (head k, 128 n-rows). Warp w owns rows 16w..16w+15, all 64 f.
// Single fp16 MMA per tile (error ~2^-11.8, well under 1e-3). Rowsum computed
// BY the MMA via a ones-row at f=64 (V tile is 72 f-rows: 64 data, row 64 = 1,
// rows 65-71 = 0). Mask applied as AND patterns on packed fp16x2 A-frags.
#define MCH 64
__global__ void __launch_bounds__(256, 2) gat_attn_mma(float* __restrict__ out) {
    __shared__ __align__(16) unsigned short s_v[2][72 * 72]; // [f-row][m], 144B rows
    __shared__ float s_hr[2][MCH];
    __shared__ uint32_t s_mb[2][128 * 2];

    const int tid  = threadIdx.x;
    const int lane = tid & 31;
    const int warp = tid >> 5;
    const int k    = blockIdx.y;
    const int n0   = blockIdx.x * 128;
    const int g    = lane >> 2;
    const int q    = lane & 3;
    const int r0   = warp * 16 + g;
    const int r1   = r0 + 8;

    const float hl0 = g_hl[k * NN + n0 + r0];
    const float hl1 = g_hl[k * NN + n0 + r1];

    float d[8][4];
#pragma unroll
    for (int nt = 0; nt < 8; nt++)
#pragma unroll
        for (int e = 0; e < 4; e++) d[nt][e] = 0.0f;
    float drs[4] = {0.f, 0.f, 0.f, 0.f};

    const uint32_t vb0 = smem_u32(s_v[0]);
    const uint32_t lm_row  = ((lane & 16) >> 1) + (lane & 7);   // 0..15
    const uint32_t lm_koff = (lane & 8) ? 16u : 0u;
    const uint32_t lm_ones = (uint32_t)(64 + (lane & 7)) * 144 + lm_koff;

    const int pf_r  = tid & 127;                  // mask row
    const int pf_w  = tid >> 7;                   // mask word (0..1)

    uint4 vreg[2];
    float hreg;
    uint32_t mreg;

    // ---- prologue: init ones/zero rows (f 64..71) in BOTH stages + chunk 0 --
    {
#pragma unroll
        for (int i = tid; i < 2 * 8 * 36; i += 256) {
            int st = i / (8 * 36);
            int rr = (i / 36) & 7;
            int cc = i % 36;
            uint32_t val = (rr == 0 && cc < 32) ? 0x3C003C00u : 0u;  // 1.0h pairs
            ((uint32_t*)s_v[st])[(64 + rr) * 36 + cc] = val;
        }
        const int m0 = 0;
#pragma unroll
        for (int u = 0; u < 2; u++) {
            int idx = u * 256 + tid;            // 0..511
            int f = idx >> 3, mo = (idx & 7) * 8;
            vreg[u] = *(const uint4*)(g_xeT_h + ((size_t)(k * FPD + f)) * NN + m0 + mo);
        }
        hreg = (tid < MCH) ? g_hr[k * NN + m0 + tid] : 0.0f;
        mreg = g_maskbT[(size_t)(m0 / 32 + pf_w) * NN + n0 + pf_r];
#pragma unroll
        for (int u = 0; u < 2; u++) {
            int idx = u * 256 + tid;
            int f = idx >> 3, mo = (idx & 7) * 8;
            *(uint4*)(s_v[0] + f * 72 + mo) = vreg[u];
        }
        if (tid < MCH) s_hr[0][tid] = hreg;
        s_mb[0][pf_r * 2 + pf_w] = mreg;
        __syncthreads();
    }

#pragma unroll 1
    for (int c = 0; c < NN / MCH; c++) {
        const int st = c & 1;
        const bool more = (c + 1 < NN / MCH);
        // ---- prefetch chunk c+1 into regs (overlaps MMA below) ----
        if (more) {
            const int m0 = (c + 1) * MCH;
#pragma unroll
            for (int u = 0; u < 2; u++) {
                int idx = u * 256 + tid;
                int f = idx >> 3, mo = (idx & 7) * 8;
                vreg[u] = *(const uint4*)(g_xeT_h + ((size_t)(k * FPD + f)) * NN + m0 + mo);
            }
            hreg = (tid < MCH) ? g_hr[k * NN + m0 + tid] : 0.0f;
            mreg = g_maskbT[(size_t)(m0 / 32 + pf_w) * NN + n0 + pf_r];
        }

        // ---- compute on stage st ----
        uint32_t mb0[2], mb1[2];
        *(uint2*)mb0 = *(const uint2*)&s_mb[st][r0 * 2];
        *(uint2*)mb1 = *(const uint2*)&s_mb[st][r1 * 2];
        const uint32_t vb = vb0 + st * (72 * 72 * 2);

#pragma unroll
        for (int t = 0; t < 4; t++) {
            // ---- P-gen (no mask sel; mask folded into fp16x2 AND below) ----
            float2 hA = *(const float2*)&s_hr[st][t * 16 + q * 2];
            float2 hB = *(const float2*)&s_hr[st][t * 16 + q * 2 + 8];
            uint32_t w0 = mb0[t >> 1], w1 = mb1[t >> 1];
            int sh = (t & 1) * 16 + q * 2;
            float p00 = pcalc(hl0, hA.x), p01 = pcalc(hl0, hA.y);
            float p02 = pcalc(hl0, hB.x), p03 = pcalc(hl0, hB.y);
            float p10 = pcalc(hl1, hA.x), p11 = pcalc(hl1, hA.y);
            float p12 = pcalc(hl1, hB.x), p13 = pcalc(hl1, hB.y);
            uint32_t ah0 = h16x2(p00, p01) & andpat(w0, sh);
            uint32_t ah1 = h16x2(p10, p11) & andpat(w1, sh);
            uint32_t ah2 = h16x2(p02, p03) & andpat(w0, sh + 8);
            uint32_t ah3 = h16x2(p12, p13) & andpat(w1, sh + 8);

            // ---- V fragments (4 n-tiles x2 + ones tile) ----
            uint32_t vA[4], vB[4], vC[4], vD[4], o0, o1;
#pragma unroll
            for (int pr = 0; pr < 4; pr++) {
                uint32_t a = (pr * 16 + lm_row) * 144 + t * 32 + lm_koff;
                LDSM4(vA[pr], vB[pr], vC[pr], vD[pr], vb + a);
            }
            LDSM2(o0, o1, vb + lm_ones + t * 32);

            // ---- 9 independent MMAs ----
#pragma unroll
            for (int pr = 0; pr < 4; pr++) {
                MMAH(d[2 * pr],     ah0, ah1, ah2, ah3, vA[pr], vB[pr]);
                MMAH(d[2 * pr + 1], ah0, ah1, ah2, ah3, vC[pr], vD[pr]);
            }
            MMAH(drs, ah0, ah1, ah2, ah3, o0, o1);
        }

        // ---- store prefetched chunk to alternate stage ----
        if (more) {
            const int st1 = 1 - st;
#pragma unroll
            for (int u = 0; u < 2; u++) {
                int idx = u * 256 + tid;
                int f = idx >> 3, mo = (idx & 7) * 8;
                *(uint4*)(s_v[st1] + f * 72 + mo) = vreg[u];
            }
            if (tid < MCH) s_hr[st1][tid] = hreg;
            s_mb[st1][pf_r * 2 + pf_w] = mreg;
            __syncthreads();
        }
    }

    // ---- epilogue: rowsums from MMA ones-column, normalize, double-ELU ----
    const float rv0 = __shfl_sync(0xFFFFFFFFu, drs[0], 0, 4);  // quad lane0: col 64
    const float rv1 = __shfl_sync(0xFFFFFFFFu, drs[2], 0, 4);
    const float i0 = 1.0f / rv0;
    const float i1 = 1.0f / rv1;
    float* o0p = out + (size_t)(n0 + r0) * KFP + k * FPD + 2 * q;
    float* o1p = out + (size_t)(n0 + r1) * KFP + k * FPD + 2 * q;
#pragma unroll
    for (int nt = 0; nt < 8; nt++) {
        float z0 = d[nt][0] * i0, z1 = d[nt][1] * i0;
        float z2 = d[nt][2] * i1, z3 = d[nt][3] * i1;
        z0 = z0 > 0.f ? z0 : expm1f(z0); z0 = z0 > 0.f ? z0 : expm1f(z0);
        z1 = z1 > 0.f ? z1 : expm1f(z1); z1 = z1 > 0.f ? z1 : expm1f(z1);
        z2 = z2 > 0.f ? z2 : expm1f(z2); z2 = z2 > 0.f ? z2 : expm1f(z2);
        z3 = z3 > 0.f ? z3 : expm1f(z3); z3 = z3 > 0.f ? z3 : expm1f(z3);
        *(float2*)(o0p + nt * 8) = make_float2(z0, z1);
        *(float2*)(o1p + nt * 8) = make_float2(z2, z3);
    }
}

// ---------------- optional: mask passthrough as float -----------------------
__global__ void mask_to_float(float* __restrict__ o, int n) {
    int i = blockIdx.x * blockDim.x + threadIdx.x;
    if (i < n) {
        int row = i >> 12, m = i & 4095;
        unsigned b = (g_maskbT[(size_t)(m >> 5) * NN + row] >> (m & 31)) & 1u;
        o[i] = (float)b;
    }
}

// ---------------- launch -----------------------------------------------------
extern "C" void kernel_launch(void* const* d_in, const int* in_sizes, int n_in,
                              void* d_out, int out_size) {
    const float* x  = (const float*)d_in[0];
    const float* W  = (const float*)d_in[1];
    const float* b  = (const float*)d_in[2];
    const float* al = (const float*)d_in[3];
    const float* ar = (const float*)d_in[4];
    const void*  m  = d_in[5];
    float* out = (float*)d_out;

    detect_mask_fmt<<<1, 32>>>((const unsigned int*)m);
    mask_canon_bits<<<(NN * NN / 32) / 256, 256>>>(m);
    gemm_xe<<<dim3(32, 8), 256>>>(x, W, b, al, ar);
    gat_attn_mma<<<dim3(32, 8), 256>>>(out);

    const int OUT_ELEMS  = NN * KFP;
    const int MASK_ELEMS = NN * NN;
    if (out_size >= OUT_ELEMS + MASK_ELEMS) {
        mask_to_float<<<(MASK_ELEMS + 255) / 256, 256>>>(out + OUT_ELEMS, MASK_ELEMS);
    }
}

// round 9
// speedup vs baseline: 1.6507x; 1.1670x over previous
#include <cuda_runtime.h>
#include <cuda_fp16.h>
#include <cstdint>

#define NN   4096
#define FF   256
#define KH   8
#define FPD  64
#define KFP  512   // K*FP
#define LOG2E 1.4426950408889634f

// ---------------- scratch (static device globals; no allocation) -------------
__device__ float g_hl[KH * NN];                   // hl[k][n] * log2(e)
__device__ uint2 g_hrB[KH * NN / 2];              // packed { fp16x2(B[m],B[m+1]), fp16x2(B2[m],B2[m+1]) }
__device__ int g_mask_fmt;                        // 0=uint8, else 4-byte words
__device__ unsigned short g_maskh[NN * NN];       // 32 MB fp16 mask (1.0 / 0.0)
__device__ unsigned short g_xeT_h[KH * FPD * NN]; // 4 MB: fp16(xe)[k][f][n]

// =================== helpers (baseline PTX only) ============================
__device__ __forceinline__ uint32_t smem_u32(const void* p) {
    uint32_t a;
    asm("{ .reg .u64 t; cvta.to.shared.u64 t, %1; cvt.u32.u64 %0, t; }" : "=r"(a) : "l"(p));
    return a;
}
__device__ __forceinline__ uint32_t h16x2(float x, float y) {
    uint32_t r;
    asm("cvt.rn.f16x2.f32 %0, %1, %2;" : "=r"(r) : "f"(y), "f"(x));
    return r;
}
__device__ __forceinline__ float ex2f(float x) {
    float r;
    asm("ex2.approx.ftz.f32 %0, %1;" : "=f"(r) : "f"(x));
    return r;
}
__device__ __forceinline__ uint32_t hmul2(uint32_t a, uint32_t b) {
    uint32_t r;
    asm("mul.f16x2 %0, %1, %2;" : "=r"(r) : "r"(a), "r"(b));
    return r;
}
__device__ __forceinline__ uint32_t hmax2(uint32_t a, uint32_t b) {
    uint32_t r;
    asm("max.f16x2 %0, %1, %2;" : "=r"(r) : "r"(a), "r"(b));
    return r;
}
__device__ __forceinline__ uint32_t lds32(uint32_t a) {
    uint32_t r;
    asm volatile("ld.shared.b32 %0, [%1];" : "=r"(r) : "r"(a));
    return r;
}
#define LDSM4(R0, R1, R2, R3, A) \
    asm volatile("ldmatrix.sync.aligned.m8n8.x4.shared.b16 {%0,%1,%2,%3}, [%4];" \
                 : "=r"(R0), "=r"(R1), "=r"(R2), "=r"(R3) : "r"(A))
#define MMAH(D, A0, A1, A2, A3, B0, B1) \
    asm volatile("mma.sync.aligned.m16n8k16.row.col.f32.f16.f16.f32 " \
                 "{%0,%1,%2,%3}, {%4,%5,%6,%7}, {%8,%9}, {%0,%1,%2,%3};" \
                 : "+f"((D)[0]), "+f"((D)[1]), "+f"((D)[2]), "+f"((D)[3]) \
                 : "r"(A0), "r"(A1), "r"(A2), "r"(A3), "r"(B0), "r"(B1))
#define CP16(dst, src) \
    asm volatile("cp.async.cg.shared.global [%0], [%1], 16;" :: "r"(dst), "l"(src) : "memory")
#define CP_COMMIT() asm volatile("cp.async.commit_group;" ::: "memory")
#define CP_WAIT0()  asm volatile("cp.async.wait_group 0;" ::: "memory")

// ---------------- Kernel 0: probe mask dtype --------------------------------
__global__ void detect_mask_fmt(const unsigned int* __restrict__ m) {
    int lane = threadIdx.x;
    bool not_i32 = false, not_f32 = false;
    for (int i = lane; i < 4096; i += 32) {
        unsigned int w = m[i];
        if (w > 1u) not_i32 = true;
        if (w != 0u && w != 0x3F800000u) not_f32 = true;
    }
    unsigned a = __ballot_sync(0xFFFFFFFFu, not_i32);
    unsigned b = __ballot_sync(0xFFFFFFFFu, not_f32);
    if (lane == 0) g_mask_fmt = (a == 0u) ? 1 : ((b == 0u) ? 2 : 0);
}

// ---------------- Kernel 0b: mask -> fp16 (1.0 / 0.0), [n][m] ----------------
__global__ void __launch_bounds__(256) mask_canon_h(const void* __restrict__ m) {
    int idx = blockIdx.x * 256 + threadIdx.x;    // 0 .. NN*NN/8-1
    int n  = idx >> 9;
    int m0 = (idx & 511) * 8;
    uint32_t h[4];
    if (g_mask_fmt != 0) {
        const uint4* p = (const uint4*)((const unsigned int*)m + (size_t)n * NN + m0);
        uint4 a = p[0], b = p[1];
        h[0] = (a.x ? 0x3C00u : 0u) | (a.y ? 0x3C000000u : 0u);
        h[1] = (a.z ? 0x3C00u : 0u) | (a.w ? 0x3C000000u : 0u);
        h[2] = (b.x ? 0x3C00u : 0u) | (b.y ? 0x3C000000u : 0u);
        h[3] = (b.z ? 0x3C00u : 0u) | (b.w ? 0x3C000000u : 0u);
    } else {
        uint2 a = *(const uint2*)((const unsigned char*)m + (size_t)n * NN + m0);
        unsigned w0 = a.x, w1 = a.y;
        h[0] = ((w0 & 0x000000FFu) ? 0x3C00u : 0u) | ((w0 & 0x0000FF00u) ? 0x3C000000u : 0u);
        h[1] = ((w0 & 0x00FF0000u) ? 0x3C00u : 0u) | ((w0 & 0xFF000000u) ? 0x3C000000u : 0u);
        h[2] = ((w1 & 0x000000FFu) ? 0x3C00u : 0u) | ((w1 & 0x0000FF00u) ? 0x3C000000u : 0u);
        h[3] = ((w1 & 0x00FF0000u) ? 0x3C00u : 0u) | ((w1 & 0xFF000000u) ? 0x3C000000u : 0u);
    }
    *(uint4*)(g_maskh + (size_t)n * NN + m0) = make_uint4(h[0], h[1], h[2], h[3]);
}

// ---------------- Kernel A: xe GEMM + fused hl + exp'd hr + fp16 transpose --
__global__ void __launch_bounds__(256) gemm_xe(const float* __restrict__ x,
                                               const float* __restrict__ W,
                                               const float* __restrict__ b,
                                               const float* __restrict__ al,
                                               const float* __restrict__ ar) {
    __shared__ float a_s[16][128];
    __shared__ float b_s[16][64];
    const int tid = threadIdx.x;
    const int tx = tid & 15;
    const int ty = tid >> 4;
    const int row0 = blockIdx.x * 128;
    const int k    = blockIdx.y;          // head
    const int col0 = k * 64;

    float acc[8][4];
#pragma unroll
    for (int i = 0; i < 8; i++)
#pragma unroll
        for (int j = 0; j < 4; j++) acc[i][j] = 0.0f;

    for (int k0 = 0; k0 < FF; k0 += 16) {
#pragma unroll
        for (int u = 0; u < 2; u++) {
            int f4 = tid * 2 + u;
            int r  = f4 >> 2;
            int c4 = f4 & 3;
            float4 v = *(const float4*)&x[(size_t)(row0 + r) * FF + k0 + c4 * 4];
            a_s[c4 * 4 + 0][r] = v.x; a_s[c4 * 4 + 1][r] = v.y;
            a_s[c4 * 4 + 2][r] = v.z; a_s[c4 * 4 + 3][r] = v.w;
        }
        {
            int o  = tid >> 2;
            int c4 = tid & 3;
            float4 v = *(const float4*)&W[(size_t)(col0 + o) * FF + k0 + c4 * 4];
            b_s[c4 * 4 + 0][o] = v.x; b_s[c4 * 4 + 1][o] = v.y;
            b_s[c4 * 4 + 2][o] = v.z; b_s[c4 * 4 + 3][o] = v.w;
        }
        __syncthreads();
#pragma unroll
        for (int kk = 0; kk < 16; kk++) {
            float a_f[8], b_f[4];
#pragma unroll
            for (int i = 0; i < 8; i++) a_f[i] = a_s[kk][ty * 8 + i];
#pragma unroll
            for (int j = 0; j < 4; j++) b_f[j] = b_s[kk][tx * 4 + j];
#pragma unroll
            for (int i = 0; i < 8; i++)
#pragma unroll
                for (int j = 0; j < 4; j++) acc[i][j] += a_f[i] * b_f[j];
        }
        __syncthreads();
    }
    float4 bias = *(const float4*)&b[col0 + tx * 4];
#pragma unroll
    for (int i = 0; i < 8; i++) {
        acc[i][0] += bias.x; acc[i][1] += bias.y;
        acc[i][2] += bias.z; acc[i][3] += bias.w;
    }
    // ---- fused hl/hr: partial dots, butterfly over tx; all lanes get sums ----
    float4 al4 = *(const float4*)&al[k * FPD + tx * 4];
    float4 ar4 = *(const float4*)&ar[k * FPD + tx * 4];
    float lsum[8], rsum[8];
#pragma unroll
    for (int i = 0; i < 8; i++) {
        float l = acc[i][0] * al4.x + acc[i][1] * al4.y + acc[i][2] * al4.z + acc[i][3] * al4.w;
        float r = acc[i][0] * ar4.x + acc[i][1] * ar4.y + acc[i][2] * ar4.z + acc[i][3] * ar4.w;
#pragma unroll
        for (int off = 8; off; off >>= 1) {
            l += __shfl_xor_sync(0xFFFFFFFFu, l, off);
            r += __shfl_xor_sync(0xFFFFFFFFu, r, off);
        }
        lsum[i] = l; rsum[i] = r;
    }
    if (tx == 0) {
#pragma unroll
        for (int i = 0; i < 8; i++)
            g_hl[k * NN + row0 + ty * 8 + i] = lsum[i] * LOG2E;
#pragma unroll
        for (int i2 = 0; i2 < 4; i2++) {
            float ra = rsum[2 * i2] * LOG2E, rb = rsum[2 * i2 + 1] * LOG2E;
            uint32_t bx = h16x2(ex2f(ra), ex2f(rb));
            uint32_t by = h16x2(ex2f(0.2f * ra), ex2f(0.2f * rb));
            g_hrB[k * (NN / 2) + (row0 + ty * 8) / 2 + i2] = make_uint2(bx, by);
        }
    }
    // ---- fp16 transpose: g_xeT_h[k][f][n] ----
#pragma unroll
    for (int j = 0; j < 4; j++) {
        uint32_t hp[4];
#pragma unroll
        for (int i2 = 0; i2 < 4; i2++)
            hp[i2] = h16x2(acc[2 * i2][j], acc[2 * i2 + 1][j]);
        size_t base = ((size_t)(k * FPD + tx * 4 + j)) * NN + row0 + ty * 8;
        *(uint4*)&g_xeT_h[base] = make_uint4(hp[0], hp[1], hp[2], hp[3]);
    }
}

// ---------------- Kernel C: attention, fp16 mma, factorized exp --------------
// p = 2^max(s, 0.2s) = max(A*B, A2*B2), A per-row (regs), B per-m (shfl bcast),
// mask = fp16 0/1 multiplied in (SMEM staged). No EX2/mask-ALU in inner loop.
// Rowsum via constant ones B-fragment MMA. cp.async double-buffered staging.
#define MCH 64
__global__ void __launch_bounds__(256, 2) gat_attn_mma(float* __restrict__ out) {
    __shared__ __align__(16) unsigned short s_v[2][64 * 64];    // [f][m] swizzled, 8KB/stage
    __shared__ __align__(16) unsigned short s_mh[2][128 * 64];  // [n][m] swizzled, 16KB/stage

    const int tid  = threadIdx.x;
    const int lane = tid & 31;
    const int warp = tid >> 5;
    const int k    = blockIdx.y;
    const int n0   = blockIdx.x * 128;
    const int g    = lane >> 2;          // 0..7
    const int q    = lane & 3;           // 0..3
    const int r0   = warp * 16 + g;
    const int r1   = r0 + 8;

    // per-row A factors (fp16x2 broadcast pairs)
    const float hl2_0 = g_hl[k * NN + n0 + r0];
    const float hl2_1 = g_hl[k * NN + n0 + r1];
    const uint32_t Ah0  = h16x2(ex2f(hl2_0), ex2f(hl2_0));
    const uint32_t A2h0 = h16x2(ex2f(0.2f * hl2_0), ex2f(0.2f * hl2_0));
    const uint32_t Ah1  = h16x2(ex2f(hl2_1), ex2f(hl2_1));
    const uint32_t A2h1 = h16x2(ex2f(0.2f * hl2_1), ex2f(0.2f * hl2_1));
    const uint32_t onesB = (lane < 4) ? 0x3C003C00u : 0u;   // rowsum B-fragment

    float d[8][4];
#pragma unroll
    for (int nt = 0; nt < 8; nt++)
#pragma unroll
        for (int e = 0; e < 4; e++) d[nt][e] = 0.0f;
    float drs[4] = {0.f, 0.f, 0.f, 0.f};

    const uint32_t svb  = smem_u32(s_v);
    const uint32_t smhb = smem_u32(s_mh);
    const uint32_t lm_row  = ((lane & 16) >> 1) + (lane & 7);   // 0..15
    const uint32_t lm_koff = (lane & 8) ? 16u : 0u;
    const uint32_t vswz = (uint32_t)(lane & 7) << 4;
    const uint32_t mswz = (uint32_t)g << 4;

    // staging decode (constant per thread)
    const int vf  = tid >> 3;            // wrong for u>0; recomputed per u below
    (void)vf;

    uint2 breg, breg_next;

    // ---- stage a chunk via cp.async (to stage st) ----
    auto stage_chunk = [&](int m0, int st) {
#pragma unroll
        for (int u = 0; u < 2; u++) {        // V: 512 x 16B
            int idx = u * 256 + tid;
            int f = idx >> 3, mo8 = (idx & 7) * 8;
            uint32_t dst = svb + st * 8192 + f * 128 + (((uint32_t)mo8 * 2) ^ ((uint32_t)(f & 7) << 4));
            CP16(dst, g_xeT_h + ((size_t)(k * FPD + f)) * NN + m0 + mo8);
        }
#pragma unroll
        for (int u = 0; u < 4; u++) {        // MH: 1024 x 16B
            int idx = u * 256 + tid;
            int row = idx >> 3, c16 = idx & 7;
            uint32_t dst = smhb + st * 16384 + row * 128 + (((uint32_t)c16 * 16) ^ ((uint32_t)(row & 7) << 4));
            CP16(dst, g_maskh + ((size_t)(n0 + row)) * NN + m0 + c16 * 8);
        }
        CP_COMMIT();
    };

    // ---- prologue: chunk 0 ----
    stage_chunk(0, 0);
    breg = g_hrB[k * (NN / 2) + lane];
    CP_WAIT0();
    __syncthreads();

#pragma unroll 1
    for (int c = 0; c < NN / MCH; c++) {
        const int st = c & 1;
        const bool more = (c + 1 < NN / MCH);
        if (more) {
            stage_chunk((c + 1) * MCH, st ^ 1);
            breg_next = g_hrB[k * (NN / 2) + (c + 1) * 32 + lane];
        }

        const uint32_t sv   = svb + st * 8192;
        const uint32_t mh0b = smhb + st * 16384 + r0 * 128;
        const uint32_t mh1b = smhb + st * 16384 + r1 * 128;

#pragma unroll
        for (int t = 0; t < 4; t++) {
            // B factors for this lane's two m-pairs (shfl broadcast)
            const int j = 8 * t + q;
            uint32_t b0x = __shfl_sync(0xFFFFFFFFu, breg.x, j);
            uint32_t b0y = __shfl_sync(0xFFFFFFFFu, breg.y, j);
            uint32_t b1x = __shfl_sync(0xFFFFFFFFu, breg.x, j + 4);
            uint32_t b1y = __shfl_sync(0xFFFFFFFFu, breg.y, j + 4);
            // mask pairs
            uint32_t moff0 = ((uint32_t)(32 * t + 4 * q)) ^ mswz;
            uint32_t moff1 = moff0 ^ 16u;
            uint32_t mh00 = lds32(mh0b + moff0);
            uint32_t mh01 = lds32(mh0b + moff1);
            uint32_t mh10 = lds32(mh1b + moff0);
            uint32_t mh11 = lds32(mh1b + moff1);
            // P fragments: max(A*B, A2*B2) * mask   (all fp16x2, FMA pipe)
            uint32_t ah0 = hmul2(hmax2(hmul2(Ah0, b0x), hmul2(A2h0, b0y)), mh00);
            uint32_t ah1 = hmul2(hmax2(hmul2(Ah1, b0x), hmul2(A2h1, b0y)), mh10);
            uint32_t ah2 = hmul2(hmax2(hmul2(Ah0, b1x), hmul2(A2h0, b1y)), mh01);
            uint32_t ah3 = hmul2(hmax2(hmul2(Ah1, b1x), hmul2(A2h1, b1y)), mh11);

            // V fragments + 9 MMAs
            const uint32_t voff = ((uint32_t)(32 * t) + lm_koff) ^ vswz;
            uint32_t vA[4], vB[4], vC[4], vD[4];
#pragma unroll
            for (int pr = 0; pr < 4; pr++)
                LDSM4(vA[pr], vB[pr], vC[pr], vD[pr], sv + (pr * 16 + lm_row) * 128 + voff);
#pragma unroll
            for (int pr = 0; pr < 4; pr++) {
                MMAH(d[2 * pr],     ah0, ah1, ah2, ah3, vA[pr], vB[pr]);
                MMAH(d[2 * pr + 1], ah0, ah1, ah2, ah3, vC[pr], vD[pr]);
            }
            MMAH(drs, ah0, ah1, ah2, ah3, onesB, onesB);
        }

        if (more) {
            CP_WAIT0();
            __syncthreads();
            breg = breg_next;
        }
    }

    // ---- epilogue: rowsums from ones-column, normalize, double-ELU, store ----
    const float rv0 = __shfl_sync(0xFFFFFFFFu, drs[0], 0, 4);
    const float rv1 = __shfl_sync(0xFFFFFFFFu, drs[2], 0, 4);
    const float i0 = 1.0f / rv0;
    const float i1 = 1.0f / rv1;
    float* o0p = out + (size_t)(n0 + r0) * KFP + k * FPD + 2 * q;
    float* o1p = out + (size_t)(n0 + r1) * KFP + k * FPD + 2 * q;
#pragma unroll
    for (int nt = 0; nt < 8; nt++) {
        float z0 = d[nt][0] * i0, z1 = d[nt][1] * i0;
        float z2 = d[nt][2] * i1, z3 = d[nt][3] * i1;
        z0 = z0 > 0.f ? z0 : expm1f(z0); z0 = z0 > 0.f ? z0 : expm1f(z0);
        z1 = z1 > 0.f ? z1 : expm1f(z1); z1 = z1 > 0.f ? z1 : expm1f(z1);
        z2 = z2 > 0.f ? z2 : expm1f(z2); z2 = z2 > 0.f ? z2 : expm1f(z2);
        z3 = z3 > 0.f ? z3 : expm1f(z3); z3 = z3 > 0.f ? z3 : expm1f(z3);
        *(float2*)(o0p + nt * 8) = make_float2(z0, z1);
        *(float2*)(o1p + nt * 8) = make_float2(z2, z3);
    }
}

// ---------------- optional: mask passthrough as float -----------------------
__global__ void mask_to_float(float* __restrict__ o, int n4) {
    int i = blockIdx.x * blockDim.x + threadIdx.x;
    if (i < n4) {
        uint2 v = *(const uint2*)(g_maskh + (size_t)i * 4);
        float4 f;
        f.x = (v.x & 0xFFFFu)     ? 1.0f : 0.0f;
        f.y = (v.x >> 16)         ? 1.0f : 0.0f;
        f.z = (v.y & 0xFFFFu)     ? 1.0f : 0.0f;
        f.w = (v.y >> 16)         ? 1.0f : 0.0f;
        *(float4*)(o + (size_t)i * 4) = f;
    }
}

// ---------------- launch -----------------------------------------------------
extern "C" void kernel_launch(void* const* d_in, const int* in_sizes, int n_in,
                              void* d_out, int out_size) {
    const float* x  = (const float*)d_in[0];
    const float* W  = (const float*)d_in[1];
    const float* b  = (const float*)d_in[2];
    const float* al = (const float*)d_in[3];
    const float* ar = (const float*)d_in[4];
    const void*  m  = d_in[5];
    float* out = (float*)d_out;

    detect_mask_fmt<<<1, 32>>>((const unsigned int*)m);
    mask_canon_h<<<(NN * NN / 8) / 256, 256>>>(m);
    gemm_xe<<<dim3(32, 8), 256>>>(x, W, b, al, ar);
    gat_attn_mma<<<dim3(32, 8), 256>>>(out);

    const int OUT_ELEMS  = NN * KFP;
    const int MASK_ELEMS = NN * NN;
    if (out_size >= OUT_ELEMS + MASK_ELEMS) {
        mask_to_float<<<(MASK_ELEMS / 4 + 255) / 256, 256>>>(out + OUT_ELEMS, MASK_ELEMS / 4);
    }
}

// round 10
// speedup vs baseline: 1.8173x; 1.1010x over previous
#include <cuda_runtime.h>
#include <cuda_fp16.h>
#include <cstdint>

#define NN   4096
#define FF   256
#define KH   8
#define FPD  64
#define KFP  512   // K*FP
#define LOG2E 1.4426950408889634f

// ---------------- scratch (static device globals; no allocation) -------------
__device__ float g_hl[KH * NN];                   // hl[k][n] * log2(e)
__device__ uint2 g_hrB[KH * NN / 2];              // packed { fp16x2(B,B), fp16x2(B2,B2) } pairs
__device__ int g_mask_fmt;                        // 0=uint8, else 4-byte words
__device__ unsigned short g_maskh[NN * NN];       // 32 MB fp16 mask (1.0 / 0.0)
__device__ unsigned short g_xeT_h[KH * FPD * NN]; // 4 MB: fp16(xe)[k][f][n]

// =================== helpers (baseline PTX only) ============================
__device__ __forceinline__ uint32_t smem_u32(const void* p) {
    uint32_t a;
    asm("{ .reg .u64 t; cvta.to.shared.u64 t, %1; cvt.u32.u64 %0, t; }" : "=r"(a) : "l"(p));
    return a;
}
__device__ __forceinline__ uint32_t h16x2(float x, float y) {
    uint32_t r;
    asm("cvt.rn.f16x2.f32 %0, %1, %2;" : "=r"(r) : "f"(y), "f"(x));
    return r;
}
__device__ __forceinline__ float ex2f(float x) {
    float r;
    asm("ex2.approx.ftz.f32 %0, %1;" : "=f"(r) : "f"(x));
    return r;
}
__device__ __forceinline__ uint32_t hmul2(uint32_t a, uint32_t b) {
    uint32_t r;
    asm("mul.f16x2 %0, %1, %2;" : "=r"(r) : "r"(a), "r"(b));
    return r;
}
__device__ __forceinline__ uint32_t hmax2(uint32_t a, uint32_t b) {
    uint32_t r;
    asm("max.f16x2 %0, %1, %2;" : "=r"(r) : "r"(a), "r"(b));
    return r;
}
__device__ __forceinline__ uint32_t lds32(uint32_t a) {
    uint32_t r;
    asm volatile("ld.shared.b32 %0, [%1];" : "=r"(r) : "r"(a));
    return r;
}
#define LDSM4(R0, R1, R2, R3, A) \
    asm volatile("ldmatrix.sync.aligned.m8n8.x4.shared.b16 {%0,%1,%2,%3}, [%4];" \
                 : "=r"(R0), "=r"(R1), "=r"(R2), "=r"(R3) : "r"(A))
#define MMAH(D, A0, A1, A2, A3, B0, B1) \
    asm volatile("mma.sync.aligned.m16n8k16.row.col.f32.f16.f16.f32 " \
                 "{%0,%1,%2,%3}, {%4,%5,%6,%7}, {%8,%9}, {%0,%1,%2,%3};" \
                 : "+f"((D)[0]), "+f"((D)[1]), "+f"((D)[2]), "+f"((D)[3]) \
                 : "r"(A0), "r"(A1), "r"(A2), "r"(A3), "r"(B0), "r"(B1))
#define CP16(dst, src) \
    asm volatile("cp.async.cg.shared.global [%0], [%1], 16;" :: "r"(dst), "l"(src) : "memory")
#define CP_COMMIT() asm volatile("cp.async.commit_group;" ::: "memory")
#define CP_WAIT(n)  asm volatile("cp.async.wait_group %0;" :: "n"(n) : "memory")

// ---------------- Kernel 0: probe mask dtype --------------------------------
__global__ void detect_mask_fmt(const unsigned int* __restrict__ m) {
    int lane = threadIdx.x;
    bool not_i32 = false, not_f32 = false;
    for (int i = lane; i < 4096; i += 32) {
        unsigned int w = m[i];
        if (w > 1u) not_i32 = true;
        if (w != 0u && w != 0x3F800000u) not_f32 = true;
    }
    unsigned a = __ballot_sync(0xFFFFFFFFu, not_i32);
    unsigned b = __ballot_sync(0xFFFFFFFFu, not_f32);
    if (lane == 0) g_mask_fmt = (a == 0u) ? 1 : ((b == 0u) ? 2 : 0);
}

// ---------------- Kernel 0b: mask -> fp16 (1.0 / 0.0), [n][m] ----------------
__global__ void __launch_bounds__(256) mask_canon_h(const void* __restrict__ m) {
    int idx = blockIdx.x * 256 + threadIdx.x;    // 0 .. NN*NN/8-1
    int n  = idx >> 9;
    int m0 = (idx & 511) * 8;
    uint32_t h[4];
    if (g_mask_fmt != 0) {
        const uint4* p = (const uint4*)((const unsigned int*)m + (size_t)n * NN + m0);
        uint4 a = p[0], b = p[1];
        h[0] = (a.x ? 0x3C00u : 0u) | (a.y ? 0x3C000000u : 0u);
        h[1] = (a.z ? 0x3C00u : 0u) | (a.w ? 0x3C000000u : 0u);
        h[2] = (b.x ? 0x3C00u : 0u) | (b.y ? 0x3C000000u : 0u);
        h[3] = (b.z ? 0x3C00u : 0u) | (b.w ? 0x3C000000u : 0u);
    } else {
        uint2 a = *(const uint2*)((const unsigned char*)m + (size_t)n * NN + m0);
        unsigned w0 = a.x, w1 = a.y;
        h[0] = ((w0 & 0x000000FFu) ? 0x3C00u : 0u) | ((w0 & 0x0000FF00u) ? 0x3C000000u : 0u);
        h[1] = ((w0 & 0x00FF0000u) ? 0x3C00u : 0u) | ((w0 & 0xFF000000u) ? 0x3C000000u : 0u);
        h[2] = ((w1 & 0x000000FFu) ? 0x3C00u : 0u) | ((w1 & 0x0000FF00u) ? 0x3C000000u : 0u);
        h[3] = ((w1 & 0x00FF0000u) ? 0x3C00u : 0u) | ((w1 & 0xFF000000u) ? 0x3C000000u : 0u);
    }
    *(uint4*)(g_maskh + (size_t)n * NN + m0) = make_uint4(h[0], h[1], h[2], h[3]);
}

// ---------------- Kernel A: xe GEMM + fused hl + exp'd hr + fp16 transpose --
__global__ void __launch_bounds__(256) gemm_xe(const float* __restrict__ x,
                                               const float* __restrict__ W,
                                               const float* __restrict__ b,
                                               const float* __restrict__ al,
                                               const float* __restrict__ ar) {
    __shared__ float a_s[16][128];
    __shared__ float b_s[16][64];
    const int tid = threadIdx.x;
    const int tx = tid & 15;
    const int ty = tid >> 4;
    const int row0 = blockIdx.x * 128;
    const int k    = blockIdx.y;          // head
    const int col0 = k * 64;

    float acc[8][4];
#pragma unroll
    for (int i = 0; i < 8; i++)
#pragma unroll
        for (int j = 0; j < 4; j++) acc[i][j] = 0.0f;

    for (int k0 = 0; k0 < FF; k0 += 16) {
#pragma unroll
        for (int u = 0; u < 2; u++) {
            int f4 = tid * 2 + u;
            int r  = f4 >> 2;
            int c4 = f4 & 3;
            float4 v = *(const float4*)&x[(size_t)(row0 + r) * FF + k0 + c4 * 4];
            a_s[c4 * 4 + 0][r] = v.x; a_s[c4 * 4 + 1][r] = v.y;
            a_s[c4 * 4 + 2][r] = v.z; a_s[c4 * 4 + 3][r] = v.w;
        }
        {
            int o  = tid >> 2;
            int c4 = tid & 3;
            float4 v = *(const float4*)&W[(size_t)(col0 + o) * FF + k0 + c4 * 4];
            b_s[c4 * 4 + 0][o] = v.x; b_s[c4 * 4 + 1][o] = v.y;
            b_s[c4 * 4 + 2][o] = v.z; b_s[c4 * 4 + 3][o] = v.w;
        }
        __syncthreads();
#pragma unroll
        for (int kk = 0; kk < 16; kk++) {
            float a_f[8], b_f[4];
#pragma unroll
            for (int i = 0; i < 8; i++) a_f[i] = a_s[kk][ty * 8 + i];
#pragma unroll
            for (int j = 0; j < 4; j++) b_f[j] = b_s[kk][tx * 4 + j];
#pragma unroll
            for (int i = 0; i < 8; i++)
#pragma unroll
                for (int j = 0; j < 4; j++) acc[i][j] += a_f[i] * b_f[j];
        }
        __syncthreads();
    }
    float4 bias = *(const float4*)&b[col0 + tx * 4];
#pragma unroll
    for (int i = 0; i < 8; i++) {
        acc[i][0] += bias.x; acc[i][1] += bias.y;
        acc[i][2] += bias.z; acc[i][3] += bias.w;
    }
    // ---- fused hl/hr: partial dots, butterfly over tx ----
    float4 al4 = *(const float4*)&al[k * FPD + tx * 4];
    float4 ar4 = *(const float4*)&ar[k * FPD + tx * 4];
    float lsum[8], rsum[8];
#pragma unroll
    for (int i = 0; i < 8; i++) {
        float l = acc[i][0] * al4.x + acc[i][1] * al4.y + acc[i][2] * al4.z + acc[i][3] * al4.w;
        float r = acc[i][0] * ar4.x + acc[i][1] * ar4.y + acc[i][2] * ar4.z + acc[i][3] * ar4.w;
#pragma unroll
        for (int off = 8; off; off >>= 1) {
            l += __shfl_xor_sync(0xFFFFFFFFu, l, off);
            r += __shfl_xor_sync(0xFFFFFFFFu, r, off);
        }
        lsum[i] = l; rsum[i] = r;
    }
    if (tx == 0) {
#pragma unroll
        for (int i = 0; i < 8; i++)
            g_hl[k * NN + row0 + ty * 8 + i] = lsum[i] * LOG2E;
#pragma unroll
        for (int i2 = 0; i2 < 4; i2++) {
            float ra = rsum[2 * i2] * LOG2E, rb = rsum[2 * i2 + 1] * LOG2E;
            uint32_t bx = h16x2(ex2f(ra), ex2f(rb));
            uint32_t by = h16x2(ex2f(0.2f * ra), ex2f(0.2f * rb));
            g_hrB[k * (NN / 2) + (row0 + ty * 8) / 2 + i2] = make_uint2(bx, by);
        }
    }
    // ---- fp16 transpose: g_xeT_h[k][f][n] ----
#pragma unroll
    for (int j = 0; j < 4; j++) {
        uint32_t hp[4];
#pragma unroll
        for (int i2 = 0; i2 < 4; i2++)
            hp[i2] = h16x2(acc[2 * i2][j], acc[2 * i2 + 1][j]);
        size_t base = ((size_t)(k * FPD + tx * 4 + j)) * NN + row0 + ty * 8;
        *(uint4*)&g_xeT_h[base] = make_uint4(hp[0], hp[1], hp[2], hp[3]);
    }
}

// ---------------- Kernel C: attention, fp16 mma, 4-stage cp.async pipeline ---
// p = 2^max(s, 0.2s) = max(A*B, A2*B2); A per-row (regs), B per-m (shfl bcast),
// mask = fp16 0/1 multiplied in. 4 SMEM stages, wait_group 2: the group waited
// on was issued 3 chunks (~3K cyc) earlier -> memory latency fully hidden.
#define MCH 64
#define NCHUNK (NN / MCH)
#define V_STAGE_B  8192     // 64 f-rows x 128B
#define MH_STAGE_B 16384    // 128 n-rows x 128B
#define SMEM_ATTN  (4 * (V_STAGE_B + MH_STAGE_B))   // 96 KB dynamic

__global__ void __launch_bounds__(256, 2) gat_attn_mma(float* __restrict__ out) {
    extern __shared__ __align__(16) char smem[];
    const uint32_t svb  = smem_u32(smem);                    // 4 x V stages
    const uint32_t smhb = svb + 4 * V_STAGE_B;               // 4 x MH stages

    const int tid  = threadIdx.x;
    const int lane = tid & 31;
    const int warp = tid >> 5;
    const int k    = blockIdx.y;
    const int n0   = blockIdx.x * 128;
    const int g    = lane >> 2;          // 0..7
    const int q    = lane & 3;           // 0..3
    const int r0   = warp * 16 + g;
    const int r1   = r0 + 8;

    // per-row A factors (fp16x2 broadcast pairs)
    const float hl2_0 = g_hl[k * NN + n0 + r0];
    const float hl2_1 = g_hl[k * NN + n0 + r1];
    const uint32_t Ah0  = h16x2(ex2f(hl2_0), ex2f(hl2_0));
    const uint32_t A2h0 = h16x2(ex2f(0.2f * hl2_0), ex2f(0.2f * hl2_0));
    const uint32_t Ah1  = h16x2(ex2f(hl2_1), ex2f(hl2_1));
    const uint32_t A2h1 = h16x2(ex2f(0.2f * hl2_1), ex2f(0.2f * hl2_1));
    const uint32_t onesB = (lane < 4) ? 0x3C003C00u : 0u;    // rowsum B-fragment

    float d[8][4];
#pragma unroll
    for (int nt = 0; nt < 8; nt++)
#pragma unroll
        for (int e = 0; e < 4; e++) d[nt][e] = 0.0f;
    float drs[4] = {0.f, 0.f, 0.f, 0.f};

    const uint32_t lm_row  = ((lane & 16) >> 1) + (lane & 7);   // 0..15
    const uint32_t lm_koff = (lane & 8) ? 16u : 0u;
    const uint32_t vswz = (uint32_t)(lane & 7) << 4;
    const uint32_t mswz = (uint32_t)g << 4;

    uint2 breg, breg_next;

    // ---- stage a chunk's V+mask via cp.async into stage st ----
    auto stage_chunk = [&](int m0, int st) {
#pragma unroll
        for (int u = 0; u < 2; u++) {        // V: 512 x 16B
            int idx = u * 256 + tid;
            int f = idx >> 3, mo8 = (idx & 7) * 8;
            uint32_t dst = svb + st * V_STAGE_B + f * 128
                         + (((uint32_t)mo8 * 2) ^ ((uint32_t)(f & 7) << 4));
            CP16(dst, g_xeT_h + ((size_t)(k * FPD + f)) * NN + m0 + mo8);
        }
#pragma unroll
        for (int u = 0; u < 4; u++) {        // MH: 1024 x 16B
            int idx = u * 256 + tid;
            int row = idx >> 3, c16 = idx & 7;
            uint32_t dst = smhb + st * MH_STAGE_B + row * 128
                         + (((uint32_t)c16 * 16) ^ ((uint32_t)(row & 7) << 4));
            CP16(dst, g_maskh + ((size_t)(n0 + row)) * NN + m0 + c16 * 8);
        }
        CP_COMMIT();
    };

    // ---- prologue: stage chunks 0,1,2 ----
    stage_chunk(0, 0);
    stage_chunk(MCH, 1);
    stage_chunk(2 * MCH, 2);
    breg = g_hrB[k * (NN / 2) + lane];

#pragma unroll 1
    for (int c = 0; c < NCHUNK; c++) {
        const int st = c & 3;
        // wait for chunk c's group (issued 3 chunks ago; <=2 groups may remain)
        CP_WAIT(2);
        __syncthreads();
        // stage chunk c+3 into the slot chunk c-1 just finished with
        if (c + 3 < NCHUNK) stage_chunk((c + 3) * MCH, (c + 3) & 3);
        if (c + 1 < NCHUNK) breg_next = g_hrB[k * (NN / 2) + (c + 1) * 32 + lane];

        const uint32_t sv   = svb + st * V_STAGE_B;
        const uint32_t mh0b = smhb + st * MH_STAGE_B + r0 * 128;
        const uint32_t mh1b = smhb + st * MH_STAGE_B + r1 * 128;

#pragma unroll
        for (int t = 0; t < 4; t++) {
            // B factors for this lane's two m-pairs (shfl broadcast)
            const int j = 8 * t + q;
            uint32_t b0x = __shfl_sync(0xFFFFFFFFu, breg.x, j);
            uint32_t b0y = __shfl_sync(0xFFFFFFFFu, breg.y, j);
            uint32_t b1x = __shfl_sync(0xFFFFFFFFu, breg.x, j + 4);
            uint32_t b1y = __shfl_sync(0xFFFFFFFFu, breg.y, j + 4);
            // mask pairs
            uint32_t moff0 = ((uint32_t)(32 * t + 4 * q)) ^ mswz;
            uint32_t moff1 = moff0 ^ 16u;
            uint32_t mh00 = lds32(mh0b + moff0);
            uint32_t mh01 = lds32(mh0b + moff1);
            uint32_t mh10 = lds32(mh1b + moff0);
            uint32_t mh11 = lds32(mh1b + moff1);
            // P fragments: max(A*B, A2*B2) * mask   (all fp16x2, FMA pipe)
            uint32_t ah0 = hmul2(hmax2(hmul2(Ah0, b0x), hmul2(A2h0, b0y)), mh00);
            uint32_t ah1 = hmul2(hmax2(hmul2(Ah1, b0x), hmul2(A2h1, b0y)), mh10);
            uint32_t ah2 = hmul2(hmax2(hmul2(Ah0, b1x), hmul2(A2h0, b1y)), mh01);
            uint32_t ah3 = hmul2(hmax2(hmul2(Ah1, b1x), hmul2(A2h1, b1y)), mh11);

            // V fragments + 9 MMAs
            const uint32_t voff = ((uint32_t)(32 * t) + lm_koff) ^ vswz;
            uint32_t vA[4], vB[4], vC[4], vD[4];
#pragma unroll
            for (int pr = 0; pr < 4; pr++)
                LDSM4(vA[pr], vB[pr], vC[pr], vD[pr], sv + (pr * 16 + lm_row) * 128 + voff);
#pragma unroll
            for (int pr = 0; pr < 4; pr++) {
                MMAH(d[2 * pr],     ah0, ah1, ah2, ah3, vA[pr], vB[pr]);
                MMAH(d[2 * pr + 1], ah0, ah1, ah2, ah3, vC[pr], vD[pr]);
            }
            MMAH(drs, ah0, ah1, ah2, ah3, onesB, onesB);
        }
        breg = breg_next;
    }

    // ---- epilogue: rowsums from ones-column, normalize, double-ELU, store ----
    const float rv0 = __shfl_sync(0xFFFFFFFFu, drs[0], 0, 4);
    const float rv1 = __shfl_sync(0xFFFFFFFFu, drs[2], 0, 4);
    const float i0 = 1.0f / rv0;
    const float i1 = 1.0f / rv1;
    float* o0p = out + (size_t)(n0 + r0) * KFP + k * FPD + 2 * q;
    float* o1p = out + (size_t)(n0 + r1) * KFP + k * FPD + 2 * q;
#pragma unroll
    for (int nt = 0; nt < 8; nt++) {
        float z0 = d[nt][0] * i0, z1 = d[nt][1] * i0;
        float z2 = d[nt][2] * i1, z3 = d[nt][3] * i1;
        z0 = z0 > 0.f ? z0 : expm1f(z0); z0 = z0 > 0.f ? z0 : expm1f(z0);
        z1 = z1 > 0.f ? z1 : expm1f(z1); z1 = z1 > 0.f ? z1 : expm1f(z1);
        z2 = z2 > 0.f ? z2 : expm1f(z2); z2 = z2 > 0.f ? z2 : expm1f(z2);
        z3 = z3 > 0.f ? z3 : expm1f(z3); z3 = z3 > 0.f ? z3 : expm1f(z3);
        *(float2*)(o0p + nt * 8) = make_float2(z0, z1);
        *(float2*)(o1p + nt * 8) = make_float2(z2, z3);
    }
}

// ---------------- optional: mask passthrough as float -----------------------
__global__ void mask_to_float(float* __restrict__ o, int n4) {
    int i = blockIdx.x * blockDim.x + threadIdx.x;
    if (i < n4) {
        uint2 v = *(const uint2*)(g_maskh + (size_t)i * 4);
        float4 f;
        f.x = (v.x & 0xFFFFu)     ? 1.0f : 0.0f;
        f.y = (v.x >> 16)         ? 1.0f : 0.0f;
        f.z = (v.y & 0xFFFFu)     ? 1.0f : 0.0f;
        f.w = (v.y >> 16)         ? 1.0f : 0.0f;
        *(float4*)(o + (size_t)i * 4) = f;
    }
}

// ---------------- launch -----------------------------------------------------
extern "C" void kernel_launch(void* const* d_in, const int* in_sizes, int n_in,
                              void* d_out, int out_size) {
    const float* x  = (const float*)d_in[0];
    const float* W  = (const float*)d_in[1];
    const float* b  = (const float*)d_in[2];
    const float* al = (const float*)d_in[3];
    const float* ar = (const float*)d_in[4];
    const void*  m  = d_in[5];
    float* out = (float*)d_out;

    cudaFuncSetAttribute(gat_attn_mma, cudaFuncAttributeMaxDynamicSharedMemorySize, SMEM_ATTN);

    detect_mask_fmt<<<1, 32>>>((const unsigned int*)m);
    mask_canon_h<<<(NN * NN / 8) / 256, 256>>>(m);
    gemm_xe<<<dim3(32, 8), 256>>>(x, W, b, al, ar);
    gat_attn_mma<<<dim3(32, 8), 256, SMEM_ATTN>>>(out);

    const int OUT_ELEMS  = NN * KFP;
    const int MASK_ELEMS = NN * NN;
    if (out_size >= OUT_ELEMS + MASK_ELEMS) {
        mask_to_float<<<(MASK_ELEMS / 4 + 255) / 256, 256>>>(out + OUT_ELEMS, MASK_ELEMS / 4);
    }
}